// round 15
// baseline (speedup 1.0000x reference)
#include <cuda_runtime.h>
#include <cuda_bf16.h>
#include <cstdint>

// ---------------------------------------------------------------------------
// Grouped per-filter 3x3 valid conv on int8-valued data with TFLite requant.
//   acc[f,j,k] = sum_{m,n,o} x[f,j+m,k+n,o] * w[f,m,n,o] + bias[f]
//
// R15 = R10 (best e2e: 191.0us) + selective streaming loads:
//   - interior rows of each band (read exactly once chip-wide): __ldcs
//     (evict-first; R8 showed the streaming policy sustains ~6.27 TB/s vs
//      ~5.92 TB/s for default policy)
//   - the 4 boundary rows shared with neighbor bands: default loads, so the
//     serpentine-scan L2 halo reuse (R9) keeps traffic at ~1.11 GB.
// Everything else byte-identical to R10: TJ=19 x 14 bands, CTA-wide
// coalesced row load+pack, ping-pong smem stage (1 barrier/row), 144
// dp4a/pixel-row, shfl horizontal combine, rolling vertical partials,
// parallel prep kernel. Exact integer math; output float32.
// ---------------------------------------------------------------------------

#define F_DIM 64
#define H_DIM 256
#define W_DIM 256
#define CIN   64
#define HO_   254
#define WO_   254
#define TJ    19
#define NBANDS 14          // 14*19 = 266 >= 254
#define NTHR  288          // 9 warps x 30 cols = 270 >= 254

#define MODE_I8   0
#define MODE_I32  1
#define MODE_F32  2
#define MODE_BF16 3

#define PIX_STRIDE 20      // words per pixel in stage (16 data + 4 pad)
#define STAGE_WORDS (W_DIM * PIX_STRIDE)   // 5120 words = 20 KB per buffer

__device__ int g_mode, g_red, g_tsh, g_ozp;
__device__ int g_bias[F_DIM];
__device__ int g_wpack[F_DIM * 144];

__device__ __forceinline__ int pack4(int b0, int b1, int b2, int b3) {
    return __byte_perm(__byte_perm(b0, b1, 0x0040),
                       __byte_perm(b2, b3, 0x0040), 0x5410);
}

__device__ __forceinline__ bool half_is_smallint(unsigned h) {
    if (h == 0) return true;
    float v = __bfloat162float(__ushort_as_bfloat16((unsigned short)h));
    return isfinite(v) && fabsf(v) <= 128.0f && v == rintf(v) && v != 0.0f;
}

__device__ __forceinline__ int sniff_mode(const int* p) {
    int ci = 0, cf = 0, cb = 0, c8 = 0;
    #pragma unroll 1
    for (int k = 0; k < 64; ++k) {
        int v = p[k];
        if (v == 0) continue;
        if (v >= -128 && v <= 127) { ++ci; continue; }
        float fv = __int_as_float(v);
        if (isfinite(fv) && fabsf(fv) <= 128.0f && fv == rintf(fv) && fv != 0.0f) { ++cf; continue; }
        unsigned u = (unsigned)v;
        if (half_is_smallint(u & 0xFFFFu) && half_is_smallint(u >> 16)) { ++cb; continue; }
        ++c8;
    }
    int best = MODE_I8, bc = c8;
    if (ci > bc) { best = MODE_I32;  bc = ci; }
    if (cf > bc) { best = MODE_F32;  bc = cf; }
    if (cb > bc) { best = MODE_BF16; bc = cb; }
    return best;
}

// ---------------------------------------------------------------------------
// Prep: 64 blocks x 144 threads; block f packs filter f, block 0 decodes
// scalars + bias. Each block sniffs the mode itself (x head words, L2-hot).
// ---------------------------------------------------------------------------
__global__ void prep_kernel(const int* __restrict__ x, const char* __restrict__ w,
                            const int* __restrict__ bias,
                            const int* __restrict__ s0, const int* __restrict__ s1,
                            const int* __restrict__ s2)
{
    __shared__ int s_mode;
    const int f   = blockIdx.x;
    const int tid = threadIdx.x;

    if (tid == 0) {
        const int mode = sniff_mode(x);
        s_mode = mode;
        if (f == 0) {
            g_mode = mode;

            int qm, expv, ozp;
            int wv[3] = { s0[0], s1[0], s2[0] };
            int nh = 0, hi = -1;
            for (int i = 0; i < 3; ++i)
                if (wv[i] > 100000 || wv[i] < -100000) { ++nh; hi = i; }
            if (nh == 1 && wv[hi] > 0) {
                qm = wv[hi];
                int a = -1, b = -1;
                for (int i = 0; i < 3; ++i) if (i != hi) { if (a < 0) a = i; else b = i; }
                expv = wv[a]; ozp = wv[b];
            } else {
                float fv[3] = { __int_as_float(wv[0]), __int_as_float(wv[1]), __int_as_float(wv[2]) };
                int nh2 = 0, hi2 = -1;
                for (int i = 0; i < 3; ++i)
                    if (isfinite(fv[i]) && fabsf(fv[i]) > 100000.0f) { ++nh2; hi2 = i; }
                if (nh2 == 1 && fv[hi2] > 0.0f) {
                    qm = (int)(long long)fv[hi2];
                    int a = -1, b = -1;
                    for (int i = 0; i < 3; ++i) if (i != hi2) { if (a < 0) a = i; else b = i; }
                    expv = (int)fv[a]; ozp = (int)fv[b];
                } else {
                    float bv[3];
                    for (int i = 0; i < 3; ++i)
                        bv[i] = __bfloat162float(__ushort_as_bfloat16((unsigned short)(wv[i] & 0xFFFF)));
                    int hi3 = 0;
                    for (int i = 1; i < 3; ++i) if (fabsf(bv[i]) > fabsf(bv[hi3])) hi3 = i;
                    qm = (int)(long long)bv[hi3];
                    int a = -1, b = -1;
                    for (int i = 0; i < 3; ++i) if (i != hi3) { if (a < 0) a = i; else b = i; }
                    expv = (int)bv[a]; ozp = (int)bv[b];
                }
            }
            g_red = (qm < 2147418112) ? ((qm + (1 << 15)) >> 16) : 32767;
            g_tsh = 15 - expv;
            g_ozp = ozp;
        }
    }
    __syncthreads();
    const int mode = s_mode;

    if (f == 0 && tid < F_DIM) {
        int v = bias[tid];
        int bv;
        if (mode == MODE_I8 || mode == MODE_I32) {
            if (v >= -(1 << 20) && v <= (1 << 20)) bv = v;
            else {
                float fb = __int_as_float(v);
                bv = (isfinite(fb) && fabsf(fb) <= 1048576.0f && fb == rintf(fb))
                     ? (int)fb
                     : (int)__bfloat162float(((const __nv_bfloat16*)bias)[tid]);
            }
        } else if (mode == MODE_F32) {
            float fb = __int_as_float(v);
            bv = (isfinite(fb) && fabsf(fb) <= 1048576.0f && fb == rintf(fb))
                 ? (int)fb : v;
        } else {
            bv = (int)__bfloat162float(((const __nv_bfloat16*)bias)[tid]);
        }
        g_bias[tid] = bv;
    }

    {
        const int i = f * 144 + tid;
        int pw;
        if (mode == MODE_I8) {
            pw = ((const int*)w)[i];
        } else if (mode == MODE_I32) {
            int4 v = ((const int4*)w)[i];
            pw = pack4(v.x, v.y, v.z, v.w);
        } else if (mode == MODE_F32) {
            float4 v = ((const float4*)w)[i];
            pw = pack4(__float2int_rn(v.x), __float2int_rn(v.y),
                       __float2int_rn(v.z), __float2int_rn(v.w));
        } else {
            uint2 v = ((const uint2*)w)[i];
            pw = pack4(__float2int_rn(__uint_as_float(v.x << 16)),
                       __float2int_rn(__uint_as_float(v.x & 0xFFFF0000u)),
                       __float2int_rn(__uint_as_float(v.y << 16)),
                       __float2int_rn(__uint_as_float(v.y & 0xFFFF0000u)));
        }
        g_wpack[i] = pw;
    }
}

// ---------------------------------------------------------------------------
// Phase A: coalesced load + pack one image row into registers.
//   STREAM=true  -> __ldcs (evict-first; rows read exactly once chip-wide)
//   STREAM=false -> default policy (boundary rows reused via L2 by the
//                   serpentine-adjacent band)
// Phase B: store packed words to the smem stage (conflict-free layout).
// ---------------------------------------------------------------------------

template<bool STREAM> __device__ __forceinline__ int4   ld4i(const int4* p)   { return STREAM ? __ldcs(p) : *p; }
template<bool STREAM> __device__ __forceinline__ float4 ld4f(const float4* p) { return STREAM ? __ldcs(p) : *p; }
template<bool STREAM> __device__ __forceinline__ uint4  ld4u(const uint4* p)  { return STREAM ? __ldcs(p) : *p; }

template<int MODE, bool STREAM>
__device__ __forceinline__ void phaseA(const char* __restrict__ xrow, int tid,
                                       int pw[16])
{
    if (MODE == MODE_I32) {
        #pragma unroll
        for (int i = 0; i < 15; ++i) {
            int w = i * NTHR + tid;
            if (w < 4096) {
                int4 v = ld4i<STREAM>((const int4*)xrow + w);
                pw[i] = pack4(v.x, v.y, v.z, v.w);
            }
        }
    } else if (MODE == MODE_F32) {
        #pragma unroll
        for (int i = 0; i < 15; ++i) {
            int w = i * NTHR + tid;
            if (w < 4096) {
                float4 v = ld4f<STREAM>((const float4*)xrow + w);
                pw[i] = pack4(__float2int_rn(v.x), __float2int_rn(v.y),
                              __float2int_rn(v.z), __float2int_rn(v.w));
            }
        }
    } else if (MODE == MODE_I8) {
        #pragma unroll
        for (int i = 0; i < 4; ++i) {
            int g = i * NTHR + tid;
            if (g < 1024) {
                int4 v = ld4i<STREAM>((const int4*)xrow + g);
                pw[i * 4 + 0] = v.x; pw[i * 4 + 1] = v.y;
                pw[i * 4 + 2] = v.z; pw[i * 4 + 3] = v.w;
            }
        }
    } else {  // BF16
        #pragma unroll
        for (int i = 0; i < 8; ++i) {
            int g = i * NTHR + tid;
            if (g < 2048) {
                uint4 v = ld4u<STREAM>((const uint4*)xrow + g);
                pw[i * 2 + 0] = pack4(__float2int_rn(__uint_as_float(v.x << 16)),
                                      __float2int_rn(__uint_as_float(v.x & 0xFFFF0000u)),
                                      __float2int_rn(__uint_as_float(v.y << 16)),
                                      __float2int_rn(__uint_as_float(v.y & 0xFFFF0000u)));
                pw[i * 2 + 1] = pack4(__float2int_rn(__uint_as_float(v.z << 16)),
                                      __float2int_rn(__uint_as_float(v.z & 0xFFFF0000u)),
                                      __float2int_rn(__uint_as_float(v.w << 16)),
                                      __float2int_rn(__uint_as_float(v.w & 0xFFFF0000u)));
            }
        }
    }
}

template<int MODE>
__device__ __forceinline__ void phaseB(int* __restrict__ xstage, int tid,
                                       const int pw[16])
{
    if (MODE == MODE_I32 || MODE == MODE_F32) {
        #pragma unroll
        for (int i = 0; i < 15; ++i) {
            int w = i * NTHR + tid;
            if (w < 4096)
                xstage[(w >> 4) * PIX_STRIDE + (w & 15)] = pw[i];
        }
    } else if (MODE == MODE_I8) {
        #pragma unroll
        for (int i = 0; i < 4; ++i) {
            int g = i * NTHR + tid;
            if (g < 1024) {
                int base = (g >> 2) * PIX_STRIDE + (g & 3) * 4;
                #pragma unroll
                for (int j = 0; j < 4; ++j) xstage[base + j] = pw[i * 4 + j];
            }
        }
    } else {  // BF16
        #pragma unroll
        for (int i = 0; i < 8; ++i) {
            int g = i * NTHR + tid;
            if (g < 2048) {
                int base = (g >> 3) * PIX_STRIDE + (g & 7) * 2;
                xstage[base + 0] = pw[i * 2 + 0];
                xstage[base + 1] = pw[i * 2 + 1];
            }
        }
    }
}

// ---------------------------------------------------------------------------

template<int MODE>
__device__ __noinline__ void run_conv(const char* __restrict__ xb,
                                      float* __restrict__ outv, int L,
                                      int* __restrict__ swp,
                                      int* __restrict__ stage)
{
    const int band = blockIdx.x;
    const int f    = blockIdx.y;
    const int tid  = threadIdx.x;
    const int wid  = tid >> 5;
    const int lane = tid & 31;

    if (tid < 144) swp[tid] = g_wpack[f * 144 + tid];

    const int red  = g_red;
    const int tsh  = g_tsh;
    const int ozp  = g_ozp;
    const int bfil = g_bias[f];
    const long long rnd = 1LL << (tsh - 1);

    const int j0    = band * TJ;
    const int jend  = (j0 + TJ < HO_) ? (j0 + TJ) : HO_;  // exclusive output rows
    const int rlast = jend + 1;                            // last input row
    const int nrows = rlast - j0 + 1;
    const bool desc = (band & 1);                          // serpentine scan

    const int gcol = 30 * wid + lane;
    const int pcol = (gcol < W_DIM) ? gcol : (W_DIM - 1);
    const bool valid = (lane < 30) && (gcol < WO_);

    const int E = (MODE == MODE_I8) ? 1 : (MODE == MODE_BF16) ? 2 : 4;
    const size_t rs = (size_t)W_DIM * CIN * E;
    const char* xf = xb + (size_t)f * H_DIM * rs;

    int pw[16];
    // prologue row is a boundary row (first of the scan) -> default policy
    phaseA<MODE, false>(xf + (size_t)(desc ? rlast : j0) * rs, tid, pw);

    int s1 = 0, s2 = 0;   // rolling vertical partials

    for (int it = 0; it < nrows; ++it) {
        const int r = desc ? (rlast - it) : (j0 + it);
        int* buf = stage + (it & 1) * STAGE_WORDS;
        phaseB<MODE>(buf, tid, pw);                 // stage row r

        if (it + 1 < nrows) {                       // issue next row's LDGs early
            const int rn = desc ? (r - 1) : (r + 1);
            // boundary rows (shared with adjacent bands): j0, j0+1, rlast-1,
            // rlast -> default policy (L2 reuse). interior rows: streaming.
            const char* p = xf + (size_t)rn * rs;
            if (rn > j0 + 1 && rn < rlast - 1) phaseA<MODE, true >(p, tid, pw);
            else                               phaseA<MODE, false>(p, tid, pw);
        }

        __syncthreads();                            // row r visible (single barrier)

        // read own pixel column (conflict-free LDS.128: (5p+k)%8 all distinct)
        int xc[16];
        {
            const int4* xs4 = (const int4*)buf;
            const int b4 = pcol * (PIX_STRIDE / 4);
            #pragma unroll
            for (int k = 0; k < 4; ++k) {
                int4 v = xs4[b4 + k];
                xc[k * 4 + 0] = v.x; xc[k * 4 + 1] = v.y;
                xc[k * 4 + 2] = v.z; xc[k * 4 + 3] = v.w;
            }
        }

        // 9 tap dot-products over 64 channels (144 dp4a)
        int y[9];
        #pragma unroll
        for (int t = 0; t < 9; ++t) {
            const int4 w0 = ((const int4*)swp)[t * 4 + 0];
            const int4 w1 = ((const int4*)swp)[t * 4 + 1];
            const int4 w2 = ((const int4*)swp)[t * 4 + 2];
            const int4 w3 = ((const int4*)swp)[t * 4 + 3];
            int a = 0;
            a = __dp4a(xc[0],  w0.x, a);  a = __dp4a(xc[1],  w0.y, a);
            a = __dp4a(xc[2],  w0.z, a);  a = __dp4a(xc[3],  w0.w, a);
            a = __dp4a(xc[4],  w1.x, a);  a = __dp4a(xc[5],  w1.y, a);
            a = __dp4a(xc[6],  w1.z, a);  a = __dp4a(xc[7],  w1.w, a);
            a = __dp4a(xc[8],  w2.x, a);  a = __dp4a(xc[9],  w2.y, a);
            a = __dp4a(xc[10], w2.z, a);  a = __dp4a(xc[11], w2.w, a);
            a = __dp4a(xc[12], w3.x, a);  a = __dp4a(xc[13], w3.y, a);
            a = __dp4a(xc[14], w3.z, a);  a = __dp4a(xc[15], w3.w, a);
            y[t] = a;
        }

        // horizontal (n) combine
        int u0, u1, u2;
        {
            int a1 = __shfl_down_sync(0xffffffffu, y[1], 1);
            int a2 = __shfl_down_sync(0xffffffffu, y[2], 2);
            u0 = y[0] + a1 + a2;
            int b1 = __shfl_down_sync(0xffffffffu, y[4], 1);
            int b2 = __shfl_down_sync(0xffffffffu, y[5], 2);
            u1 = y[3] + b1 + b2;
            int c1 = __shfl_down_sync(0xffffffffu, y[7], 1);
            int c2 = __shfl_down_sync(0xffffffffu, y[8], 2);
            u2 = y[6] + c1 + c2;
        }

        // vertical (m) rolling combine:
        //   asc : out(j=r-2) = u2(r) + u1(r-1) + u0(r-2)
        //   desc: out(j=r)   = u0(r) + u1(r+1) + u2(r+2)
        int done;
        if (desc) { done = u0 + s1; s1 = u1 + s2; s2 = u2; }
        else      { done = s2 + u2; s2 = s1 + u1; s1 = u0; }

        if (it >= 2 && valid) {
            const int j = desc ? r : (r - 2);
            long long a64 = (long long)(done + bfil) * (long long)red + rnd;
            int res = (int)(a64 >> tsh) + ozp;
            res = res < -128 ? -128 : (res > 127 ? 127 : res);
            size_t oidx = ((size_t)(f * HO_ + j) * WO_ + gcol) * (size_t)L;
            for (int l = 0; l < L; ++l) __stcs(&outv[oidx + l], (float)res);
        }
    }
}

__global__ void __launch_bounds__(NTHR, 3)
conv_any(const char* __restrict__ xb, float* __restrict__ outv, int L)
{
    __shared__ __align__(16) int swp[144];
    __shared__ __align__(16) int stage[2 * STAGE_WORDS];   // 40 KB ping-pong

    const int mode = g_mode;   // uniform across grid
    if (mode == MODE_I32)      run_conv<MODE_I32 >(xb, outv, L, swp, stage);
    else if (mode == MODE_I8)  run_conv<MODE_I8  >(xb, outv, L, swp, stage);
    else if (mode == MODE_F32) run_conv<MODE_F32 >(xb, outv, L, swp, stage);
    else                       run_conv<MODE_BF16>(xb, outv, L, swp, stage);
}

// ---------------------------------------------------------------------------

extern "C" void kernel_launch(void* const* d_in, const int* in_sizes, int n_in,
                              void* d_out, int out_size)
{
    // Identify inputs BY SIZE (ordering-agnostic).
    const void* x = nullptr; const void* w = nullptr; const void* b = nullptr;
    const void* s[3] = {nullptr, nullptr, nullptr};
    int ns = 0;
    int ximax = 0;
    for (int i = 1; i < n_in; ++i)
        if (in_sizes[i] > in_sizes[ximax]) ximax = i;
    for (int i = 0; i < n_in; ++i) {
        if (i == ximax)                 x = d_in[i];
        else if (in_sizes[i] == 36864) w = d_in[i];
        else if (in_sizes[i] == 64)    b = d_in[i];
        else if (in_sizes[i] == 1 && ns < 3) s[ns++] = d_in[i];
    }
    if (!x || !w || !b || ns < 3) {
        x = d_in[0]; w = d_in[1]; b = d_in[2];
        s[0] = d_in[3]; s[1] = d_in[4]; s[2] = d_in[5];
    }

    int L = out_size / (F_DIM * HO_ * WO_);
    if (L < 1) L = 1;

    prep_kernel<<<F_DIM, 144>>>((const int*)x, (const char*)w, (const int*)b,
                                (const int*)s[0], (const int*)s[1], (const int*)s[2]);

    dim3 grid(NBANDS, F_DIM);
    conv_any<<<grid, NTHR>>>((const char*)x, (float*)d_out, L);
}

// round 16
// speedup vs baseline: 1.0130x; 1.0130x over previous
#include <cuda_runtime.h>
#include <cuda_bf16.h>
#include <cstdint>

// ---------------------------------------------------------------------------
// Grouped per-filter 3x3 valid conv on int8-valued data with TFLite requant.
//   acc[f,j,k] = sum_{m,n,o} x[f,j+m,k+n,o] * w[f,m,n,o] + bias[f]
//
// FINAL (= R10, best measured: 191.0us e2e, 187.6us conv, DRAM 74.6%):
//  - prep kernel (64 blocks x 144 thr): sniffs storage dtype of the widened
//    tensors (int8/int32/f32/bf16) from bit patterns, decodes requant
//    scalars, converts bias, pre-packs all weights to int8x4 words.
//  - conv kernel: per (filter, 19-row band) CTA; per image row the CTA loads
//    the full 256-pixel row COALESCED (LDG.128, packing to int8 in flight),
//    stages it in a ping-pong smem buffer (80B/pixel stride -> conflict-free
//    LDS.128 readback), one __syncthreads per row; each thread computes 9
//    tap dot-products (144 dp4a), horizontal 3-tap combine via shfl, vertical
//    3-tap combine via rolling register partials; exact int64 requant.
//  - serpentine band order (odd bands scan descending) makes the 2-row halo
//    shared by adjacent bands L2-hot -> traffic ~1.11 GB (min 1.09 GB).
//  - verified experimentally around this optimum: warp-private staging,
//    higher occupancy, band-count changes, perfect-wave grids, and streaming
//    load policies are all neutral or regressions (R11-R15).
// Exact integer math throughout; output float32.
// ---------------------------------------------------------------------------

#define F_DIM 64
#define H_DIM 256
#define W_DIM 256
#define CIN   64
#define HO_   254
#define WO_   254
#define TJ    19
#define NBANDS 14          // 14*19 = 266 >= 254
#define NTHR  288          // 9 warps x 30 cols = 270 >= 254

#define MODE_I8   0
#define MODE_I32  1
#define MODE_F32  2
#define MODE_BF16 3

#define PIX_STRIDE 20      // words per pixel in stage (16 data + 4 pad)
#define STAGE_WORDS (W_DIM * PIX_STRIDE)   // 5120 words = 20 KB per buffer

__device__ int g_mode, g_red, g_tsh, g_ozp;
__device__ int g_bias[F_DIM];
__device__ int g_wpack[F_DIM * 144];

__device__ __forceinline__ int pack4(int b0, int b1, int b2, int b3) {
    return __byte_perm(__byte_perm(b0, b1, 0x0040),
                       __byte_perm(b2, b3, 0x0040), 0x5410);
}

__device__ __forceinline__ bool half_is_smallint(unsigned h) {
    if (h == 0) return true;
    float v = __bfloat162float(__ushort_as_bfloat16((unsigned short)h));
    return isfinite(v) && fabsf(v) <= 128.0f && v == rintf(v) && v != 0.0f;
}

__device__ __forceinline__ int sniff_mode(const int* p) {
    int ci = 0, cf = 0, cb = 0, c8 = 0;
    #pragma unroll 1
    for (int k = 0; k < 64; ++k) {
        int v = p[k];
        if (v == 0) continue;
        if (v >= -128 && v <= 127) { ++ci; continue; }
        float fv = __int_as_float(v);
        if (isfinite(fv) && fabsf(fv) <= 128.0f && fv == rintf(fv) && fv != 0.0f) { ++cf; continue; }
        unsigned u = (unsigned)v;
        if (half_is_smallint(u & 0xFFFFu) && half_is_smallint(u >> 16)) { ++cb; continue; }
        ++c8;
    }
    int best = MODE_I8, bc = c8;
    if (ci > bc) { best = MODE_I32;  bc = ci; }
    if (cf > bc) { best = MODE_F32;  bc = cf; }
    if (cb > bc) { best = MODE_BF16; bc = cb; }
    return best;
}

// ---------------------------------------------------------------------------
// Prep: 64 blocks x 144 threads; block f packs filter f, block 0 decodes
// scalars + bias. Each block sniffs the mode itself (x head words, L2-hot).
// ---------------------------------------------------------------------------
__global__ void prep_kernel(const int* __restrict__ x, const char* __restrict__ w,
                            const int* __restrict__ bias,
                            const int* __restrict__ s0, const int* __restrict__ s1,
                            const int* __restrict__ s2)
{
    __shared__ int s_mode;
    const int f   = blockIdx.x;
    const int tid = threadIdx.x;

    if (tid == 0) {
        const int mode = sniff_mode(x);
        s_mode = mode;
        if (f == 0) {
            g_mode = mode;

            int qm, expv, ozp;
            int wv[3] = { s0[0], s1[0], s2[0] };
            int nh = 0, hi = -1;
            for (int i = 0; i < 3; ++i)
                if (wv[i] > 100000 || wv[i] < -100000) { ++nh; hi = i; }
            if (nh == 1 && wv[hi] > 0) {
                qm = wv[hi];
                int a = -1, b = -1;
                for (int i = 0; i < 3; ++i) if (i != hi) { if (a < 0) a = i; else b = i; }
                expv = wv[a]; ozp = wv[b];
            } else {
                float fv[3] = { __int_as_float(wv[0]), __int_as_float(wv[1]), __int_as_float(wv[2]) };
                int nh2 = 0, hi2 = -1;
                for (int i = 0; i < 3; ++i)
                    if (isfinite(fv[i]) && fabsf(fv[i]) > 100000.0f) { ++nh2; hi2 = i; }
                if (nh2 == 1 && fv[hi2] > 0.0f) {
                    qm = (int)(long long)fv[hi2];
                    int a = -1, b = -1;
                    for (int i = 0; i < 3; ++i) if (i != hi2) { if (a < 0) a = i; else b = i; }
                    expv = (int)fv[a]; ozp = (int)fv[b];
                } else {
                    float bv[3];
                    for (int i = 0; i < 3; ++i)
                        bv[i] = __bfloat162float(__ushort_as_bfloat16((unsigned short)(wv[i] & 0xFFFF)));
                    int hi3 = 0;
                    for (int i = 1; i < 3; ++i) if (fabsf(bv[i]) > fabsf(bv[hi3])) hi3 = i;
                    qm = (int)(long long)bv[hi3];
                    int a = -1, b = -1;
                    for (int i = 0; i < 3; ++i) if (i != hi3) { if (a < 0) a = i; else b = i; }
                    expv = (int)bv[a]; ozp = (int)bv[b];
                }
            }
            g_red = (qm < 2147418112) ? ((qm + (1 << 15)) >> 16) : 32767;
            g_tsh = 15 - expv;
            g_ozp = ozp;
        }
    }
    __syncthreads();
    const int mode = s_mode;

    if (f == 0 && tid < F_DIM) {
        int v = bias[tid];
        int bv;
        if (mode == MODE_I8 || mode == MODE_I32) {
            if (v >= -(1 << 20) && v <= (1 << 20)) bv = v;
            else {
                float fb = __int_as_float(v);
                bv = (isfinite(fb) && fabsf(fb) <= 1048576.0f && fb == rintf(fb))
                     ? (int)fb
                     : (int)__bfloat162float(((const __nv_bfloat16*)bias)[tid]);
            }
        } else if (mode == MODE_F32) {
            float fb = __int_as_float(v);
            bv = (isfinite(fb) && fabsf(fb) <= 1048576.0f && fb == rintf(fb))
                 ? (int)fb : v;
        } else {
            bv = (int)__bfloat162float(((const __nv_bfloat16*)bias)[tid]);
        }
        g_bias[tid] = bv;
    }

    {
        const int i = f * 144 + tid;
        int pw;
        if (mode == MODE_I8) {
            pw = ((const int*)w)[i];
        } else if (mode == MODE_I32) {
            int4 v = ((const int4*)w)[i];
            pw = pack4(v.x, v.y, v.z, v.w);
        } else if (mode == MODE_F32) {
            float4 v = ((const float4*)w)[i];
            pw = pack4(__float2int_rn(v.x), __float2int_rn(v.y),
                       __float2int_rn(v.z), __float2int_rn(v.w));
        } else {
            uint2 v = ((const uint2*)w)[i];
            pw = pack4(__float2int_rn(__uint_as_float(v.x << 16)),
                       __float2int_rn(__uint_as_float(v.x & 0xFFFF0000u)),
                       __float2int_rn(__uint_as_float(v.y << 16)),
                       __float2int_rn(__uint_as_float(v.y & 0xFFFF0000u)));
        }
        g_wpack[i] = pw;
    }
}

// ---------------------------------------------------------------------------
// Phase A: coalesced load + pack one image row into registers.
// Phase B: store packed words to the smem stage (conflict-free layout).
// ---------------------------------------------------------------------------

template<int MODE>
__device__ __forceinline__ void phaseA(const char* __restrict__ xrow, int tid,
                                       int pw[16])
{
    if (MODE == MODE_I32) {
        #pragma unroll
        for (int i = 0; i < 15; ++i) {
            int w = i * NTHR + tid;
            if (w < 4096) {
                int4 v = ((const int4*)xrow)[w];
                pw[i] = pack4(v.x, v.y, v.z, v.w);
            }
        }
    } else if (MODE == MODE_F32) {
        #pragma unroll
        for (int i = 0; i < 15; ++i) {
            int w = i * NTHR + tid;
            if (w < 4096) {
                float4 v = ((const float4*)xrow)[w];
                pw[i] = pack4(__float2int_rn(v.x), __float2int_rn(v.y),
                              __float2int_rn(v.z), __float2int_rn(v.w));
            }
        }
    } else if (MODE == MODE_I8) {
        #pragma unroll
        for (int i = 0; i < 4; ++i) {
            int g = i * NTHR + tid;
            if (g < 1024) {
                int4 v = ((const int4*)xrow)[g];
                pw[i * 4 + 0] = v.x; pw[i * 4 + 1] = v.y;
                pw[i * 4 + 2] = v.z; pw[i * 4 + 3] = v.w;
            }
        }
    } else {  // BF16
        #pragma unroll
        for (int i = 0; i < 8; ++i) {
            int g = i * NTHR + tid;
            if (g < 2048) {
                uint4 v = ((const uint4*)xrow)[g];
                pw[i * 2 + 0] = pack4(__float2int_rn(__uint_as_float(v.x << 16)),
                                      __float2int_rn(__uint_as_float(v.x & 0xFFFF0000u)),
                                      __float2int_rn(__uint_as_float(v.y << 16)),
                                      __float2int_rn(__uint_as_float(v.y & 0xFFFF0000u)));
                pw[i * 2 + 1] = pack4(__float2int_rn(__uint_as_float(v.z << 16)),
                                      __float2int_rn(__uint_as_float(v.z & 0xFFFF0000u)),
                                      __float2int_rn(__uint_as_float(v.w << 16)),
                                      __float2int_rn(__uint_as_float(v.w & 0xFFFF0000u)));
            }
        }
    }
}

template<int MODE>
__device__ __forceinline__ void phaseB(int* __restrict__ xstage, int tid,
                                       const int pw[16])
{
    if (MODE == MODE_I32 || MODE == MODE_F32) {
        #pragma unroll
        for (int i = 0; i < 15; ++i) {
            int w = i * NTHR + tid;
            if (w < 4096)
                xstage[(w >> 4) * PIX_STRIDE + (w & 15)] = pw[i];
        }
    } else if (MODE == MODE_I8) {
        #pragma unroll
        for (int i = 0; i < 4; ++i) {
            int g = i * NTHR + tid;
            if (g < 1024) {
                int base = (g >> 2) * PIX_STRIDE + (g & 3) * 4;
                #pragma unroll
                for (int j = 0; j < 4; ++j) xstage[base + j] = pw[i * 4 + j];
            }
        }
    } else {  // BF16
        #pragma unroll
        for (int i = 0; i < 8; ++i) {
            int g = i * NTHR + tid;
            if (g < 2048) {
                int base = (g >> 3) * PIX_STRIDE + (g & 7) * 2;
                xstage[base + 0] = pw[i * 2 + 0];
                xstage[base + 1] = pw[i * 2 + 1];
            }
        }
    }
}

// ---------------------------------------------------------------------------

template<int MODE>
__device__ __noinline__ void run_conv(const char* __restrict__ xb,
                                      float* __restrict__ outv, int L,
                                      int* __restrict__ swp,
                                      int* __restrict__ stage)
{
    const int band = blockIdx.x;
    const int f    = blockIdx.y;
    const int tid  = threadIdx.x;
    const int wid  = tid >> 5;
    const int lane = tid & 31;

    if (tid < 144) swp[tid] = g_wpack[f * 144 + tid];

    const int red  = g_red;
    const int tsh  = g_tsh;
    const int ozp  = g_ozp;
    const int bfil = g_bias[f];
    const long long rnd = 1LL << (tsh - 1);

    const int j0    = band * TJ;
    const int jend  = (j0 + TJ < HO_) ? (j0 + TJ) : HO_;  // exclusive output rows
    const int rlast = jend + 1;                            // last input row
    const int nrows = rlast - j0 + 1;
    const bool desc = (band & 1);                          // serpentine scan

    const int gcol = 30 * wid + lane;
    const int pcol = (gcol < W_DIM) ? gcol : (W_DIM - 1);
    const bool valid = (lane < 30) && (gcol < WO_);

    const int E = (MODE == MODE_I8) ? 1 : (MODE == MODE_BF16) ? 2 : 4;
    const size_t rs = (size_t)W_DIM * CIN * E;
    const char* xf = xb + (size_t)f * H_DIM * rs;

    int pw[16];
    phaseA<MODE>(xf + (size_t)(desc ? rlast : j0) * rs, tid, pw);   // prologue

    int s1 = 0, s2 = 0;   // rolling vertical partials

    for (int it = 0; it < nrows; ++it) {
        const int r = desc ? (rlast - it) : (j0 + it);
        int* buf = stage + (it & 1) * STAGE_WORDS;
        phaseB<MODE>(buf, tid, pw);                 // stage row r

        if (it + 1 < nrows) {                       // issue next row's LDGs early
            const int rn = desc ? (r - 1) : (r + 1);
            phaseA<MODE>(xf + (size_t)rn * rs, tid, pw);
        }

        __syncthreads();                            // row r visible (single barrier)

        // read own pixel column (conflict-free LDS.128: (5p+k)%8 all distinct)
        int xc[16];
        {
            const int4* xs4 = (const int4*)buf;
            const int b4 = pcol * (PIX_STRIDE / 4);
            #pragma unroll
            for (int k = 0; k < 4; ++k) {
                int4 v = xs4[b4 + k];
                xc[k * 4 + 0] = v.x; xc[k * 4 + 1] = v.y;
                xc[k * 4 + 2] = v.z; xc[k * 4 + 3] = v.w;
            }
        }

        // 9 tap dot-products over 64 channels (144 dp4a)
        int y[9];
        #pragma unroll
        for (int t = 0; t < 9; ++t) {
            const int4 w0 = ((const int4*)swp)[t * 4 + 0];
            const int4 w1 = ((const int4*)swp)[t * 4 + 1];
            const int4 w2 = ((const int4*)swp)[t * 4 + 2];
            const int4 w3 = ((const int4*)swp)[t * 4 + 3];
            int a = 0;
            a = __dp4a(xc[0],  w0.x, a);  a = __dp4a(xc[1],  w0.y, a);
            a = __dp4a(xc[2],  w0.z, a);  a = __dp4a(xc[3],  w0.w, a);
            a = __dp4a(xc[4],  w1.x, a);  a = __dp4a(xc[5],  w1.y, a);
            a = __dp4a(xc[6],  w1.z, a);  a = __dp4a(xc[7],  w1.w, a);
            a = __dp4a(xc[8],  w2.x, a);  a = __dp4a(xc[9],  w2.y, a);
            a = __dp4a(xc[10], w2.z, a);  a = __dp4a(xc[11], w2.w, a);
            a = __dp4a(xc[12], w3.x, a);  a = __dp4a(xc[13], w3.y, a);
            a = __dp4a(xc[14], w3.z, a);  a = __dp4a(xc[15], w3.w, a);
            y[t] = a;
        }

        // horizontal (n) combine
        int u0, u1, u2;
        {
            int a1 = __shfl_down_sync(0xffffffffu, y[1], 1);
            int a2 = __shfl_down_sync(0xffffffffu, y[2], 2);
            u0 = y[0] + a1 + a2;
            int b1 = __shfl_down_sync(0xffffffffu, y[4], 1);
            int b2 = __shfl_down_sync(0xffffffffu, y[5], 2);
            u1 = y[3] + b1 + b2;
            int c1 = __shfl_down_sync(0xffffffffu, y[7], 1);
            int c2 = __shfl_down_sync(0xffffffffu, y[8], 2);
            u2 = y[6] + c1 + c2;
        }

        // vertical (m) rolling combine:
        //   asc : out(j=r-2) = u2(r) + u1(r-1) + u0(r-2)
        //   desc: out(j=r)   = u0(r) + u1(r+1) + u2(r+2)
        int done;
        if (desc) { done = u0 + s1; s1 = u1 + s2; s2 = u2; }
        else      { done = s2 + u2; s2 = s1 + u1; s1 = u0; }

        if (it >= 2 && valid) {
            const int j = desc ? r : (r - 2);
            long long a64 = (long long)(done + bfil) * (long long)red + rnd;
            int res = (int)(a64 >> tsh) + ozp;
            res = res < -128 ? -128 : (res > 127 ? 127 : res);
            size_t oidx = ((size_t)(f * HO_ + j) * WO_ + gcol) * (size_t)L;
            for (int l = 0; l < L; ++l) __stcs(&outv[oidx + l], (float)res);
        }
    }
}

__global__ void __launch_bounds__(NTHR, 3)
conv_any(const char* __restrict__ xb, float* __restrict__ outv, int L)
{
    __shared__ __align__(16) int swp[144];
    __shared__ __align__(16) int stage[2 * STAGE_WORDS];   // 40 KB ping-pong

    const int mode = g_mode;   // uniform across grid
    if (mode == MODE_I32)      run_conv<MODE_I32 >(xb, outv, L, swp, stage);
    else if (mode == MODE_I8)  run_conv<MODE_I8  >(xb, outv, L, swp, stage);
    else if (mode == MODE_F32) run_conv<MODE_F32 >(xb, outv, L, swp, stage);
    else                       run_conv<MODE_BF16>(xb, outv, L, swp, stage);
}

// ---------------------------------------------------------------------------

extern "C" void kernel_launch(void* const* d_in, const int* in_sizes, int n_in,
                              void* d_out, int out_size)
{
    // Identify inputs BY SIZE (ordering-agnostic).
    const void* x = nullptr; const void* w = nullptr; const void* b = nullptr;
    const void* s[3] = {nullptr, nullptr, nullptr};
    int ns = 0;
    int ximax = 0;
    for (int i = 1; i < n_in; ++i)
        if (in_sizes[i] > in_sizes[ximax]) ximax = i;
    for (int i = 0; i < n_in; ++i) {
        if (i == ximax)                 x = d_in[i];
        else if (in_sizes[i] == 36864) w = d_in[i];
        else if (in_sizes[i] == 64)    b = d_in[i];
        else if (in_sizes[i] == 1 && ns < 3) s[ns++] = d_in[i];
    }
    if (!x || !w || !b || ns < 3) {
        x = d_in[0]; w = d_in[1]; b = d_in[2];
        s[0] = d_in[3]; s[1] = d_in[4]; s[2] = d_in[5];
    }

    int L = out_size / (F_DIM * HO_ * WO_);
    if (L < 1) L = 1;

    prep_kernel<<<F_DIM, 144>>>((const int*)x, (const char*)w, (const int*)b,
                                (const int*)s[0], (const int*)s[1], (const int*)s[2]);

    dim3 grid(NBANDS, F_DIM);
    conv_any<<<grid, NTHR>>>((const char*)x, (float*)d_out, L);
}

// round 17
// speedup vs baseline: 1.0656x; 1.0518x over previous
#include <cuda_runtime.h>
#include <cuda_bf16.h>
#include <cstdint>

// ---------------------------------------------------------------------------
// Grouped per-filter 3x3 valid conv on int8-valued data with TFLite requant.
//   acc[f,j,k] = sum_{m,n,o} x[f,j+m,k+n,o] * w[f,m,n,o] + bias[f]
//
// R17 = R10 conv core (best: 187.6us conv, DRAM ~75%) made SELF-CONTAINED:
// the prep kernel is folded into the conv kernel's startup (saves the prep
// launch + exec, ~3-5us of e2e overhead):
//   - mode sniff: 64 threads classify one x-word each, smem-atomic tally
//     (x[0..63] is L2-hot after the first CTA)
//   - scalars decoded by tid 0 into smem
//   - weights packed by tid<144 directly from w (same 144 loads as before,
//     conversion folded in); bias decoded per-thread (broadcast load)
// Inner loop byte-identical to R10: per (filter, 19-row band) CTA, CTA-wide
// coalesced row load+pack, ping-pong smem stage (1 barrier/row), serpentine
// band order (halo L2 reuse), 144 dp4a/pixel-row, shfl horizontal combine,
// rolling vertical partials, exact int64 requant. Output float32.
// ---------------------------------------------------------------------------

#define F_DIM 64
#define H_DIM 256
#define W_DIM 256
#define CIN   64
#define HO_   254
#define WO_   254
#define TJ    19
#define NBANDS 14          // 14*19 = 266 >= 254
#define NTHR  288          // 9 warps x 30 cols = 270 >= 254

#define MODE_I8   0
#define MODE_I32  1
#define MODE_F32  2
#define MODE_BF16 3

#define PIX_STRIDE 20      // words per pixel in stage (16 data + 4 pad)
#define STAGE_WORDS (W_DIM * PIX_STRIDE)   // 5120 words = 20 KB per buffer

__device__ __forceinline__ int pack4(int b0, int b1, int b2, int b3) {
    return __byte_perm(__byte_perm(b0, b1, 0x0040),
                       __byte_perm(b2, b3, 0x0040), 0x5410);
}

__device__ __forceinline__ bool half_is_smallint(unsigned h) {
    if (h == 0) return true;
    float v = __bfloat162float(__ushort_as_bfloat16((unsigned short)h));
    return isfinite(v) && fabsf(v) <= 128.0f && v == rintf(v) && v != 0.0f;
}

// classify one widened-int8 storage word; -1 = uninformative (zero)
__device__ __forceinline__ int classify_word(int v) {
    if (v == 0) return -1;
    if (v >= -128 && v <= 127) return MODE_I32;
    float fv = __int_as_float(v);
    if (isfinite(fv) && fabsf(fv) <= 128.0f && fv == rintf(fv)) return MODE_F32;
    unsigned u = (unsigned)v;
    if (half_is_smallint(u & 0xFFFFu) && half_is_smallint(u >> 16)) return MODE_BF16;
    return MODE_I8;
}

// ---------------------------------------------------------------------------
// Phase A: coalesced load + pack one image row into registers.
// Phase B: store packed words to the smem stage (conflict-free layout).
// ---------------------------------------------------------------------------

template<int MODE>
__device__ __forceinline__ void phaseA(const char* __restrict__ xrow, int tid,
                                       int pw[16])
{
    if (MODE == MODE_I32) {
        #pragma unroll
        for (int i = 0; i < 15; ++i) {
            int w = i * NTHR + tid;
            if (w < 4096) {
                int4 v = ((const int4*)xrow)[w];
                pw[i] = pack4(v.x, v.y, v.z, v.w);
            }
        }
    } else if (MODE == MODE_F32) {
        #pragma unroll
        for (int i = 0; i < 15; ++i) {
            int w = i * NTHR + tid;
            if (w < 4096) {
                float4 v = ((const float4*)xrow)[w];
                pw[i] = pack4(__float2int_rn(v.x), __float2int_rn(v.y),
                              __float2int_rn(v.z), __float2int_rn(v.w));
            }
        }
    } else if (MODE == MODE_I8) {
        #pragma unroll
        for (int i = 0; i < 4; ++i) {
            int g = i * NTHR + tid;
            if (g < 1024) {
                int4 v = ((const int4*)xrow)[g];
                pw[i * 4 + 0] = v.x; pw[i * 4 + 1] = v.y;
                pw[i * 4 + 2] = v.z; pw[i * 4 + 3] = v.w;
            }
        }
    } else {  // BF16
        #pragma unroll
        for (int i = 0; i < 8; ++i) {
            int g = i * NTHR + tid;
            if (g < 2048) {
                uint4 v = ((const uint4*)xrow)[g];
                pw[i * 2 + 0] = pack4(__float2int_rn(__uint_as_float(v.x << 16)),
                                      __float2int_rn(__uint_as_float(v.x & 0xFFFF0000u)),
                                      __float2int_rn(__uint_as_float(v.y << 16)),
                                      __float2int_rn(__uint_as_float(v.y & 0xFFFF0000u)));
                pw[i * 2 + 1] = pack4(__float2int_rn(__uint_as_float(v.z << 16)),
                                      __float2int_rn(__uint_as_float(v.z & 0xFFFF0000u)),
                                      __float2int_rn(__uint_as_float(v.w << 16)),
                                      __float2int_rn(__uint_as_float(v.w & 0xFFFF0000u)));
            }
        }
    }
}

template<int MODE>
__device__ __forceinline__ void phaseB(int* __restrict__ xstage, int tid,
                                       const int pw[16])
{
    if (MODE == MODE_I32 || MODE == MODE_F32) {
        #pragma unroll
        for (int i = 0; i < 15; ++i) {
            int w = i * NTHR + tid;
            if (w < 4096)
                xstage[(w >> 4) * PIX_STRIDE + (w & 15)] = pw[i];
        }
    } else if (MODE == MODE_I8) {
        #pragma unroll
        for (int i = 0; i < 4; ++i) {
            int g = i * NTHR + tid;
            if (g < 1024) {
                int base = (g >> 2) * PIX_STRIDE + (g & 3) * 4;
                #pragma unroll
                for (int j = 0; j < 4; ++j) xstage[base + j] = pw[i * 4 + j];
            }
        }
    } else {  // BF16
        #pragma unroll
        for (int i = 0; i < 8; ++i) {
            int g = i * NTHR + tid;
            if (g < 2048) {
                int base = (g >> 3) * PIX_STRIDE + (g & 7) * 2;
                xstage[base + 0] = pw[i * 2 + 0];
                xstage[base + 1] = pw[i * 2 + 1];
            }
        }
    }
}

// ---------------------------------------------------------------------------

template<int MODE>
__device__ __noinline__ void run_conv(const char* __restrict__ xb,
                                      const char* __restrict__ wb,
                                      const int*  __restrict__ bias,
                                      float* __restrict__ outv, int L,
                                      int* __restrict__ swp,
                                      int* __restrict__ stage,
                                      int red, int tsh, int ozp)
{
    const int band = blockIdx.x;
    const int f    = blockIdx.y;
    const int tid  = threadIdx.x;
    const int wid  = tid >> 5;
    const int lane = tid & 31;

    // pack this filter's 144 weight words straight from w (mode folded in)
    if (tid < 144) {
        const size_t i = (size_t)f * 144 + tid;
        int pwv;
        if (MODE == MODE_I8) {
            pwv = ((const int*)wb)[i];
        } else if (MODE == MODE_I32) {
            int4 v = ((const int4*)wb)[i];
            pwv = pack4(v.x, v.y, v.z, v.w);
        } else if (MODE == MODE_F32) {
            float4 v = ((const float4*)wb)[i];
            pwv = pack4(__float2int_rn(v.x), __float2int_rn(v.y),
                        __float2int_rn(v.z), __float2int_rn(v.w));
        } else {
            uint2 v = ((const uint2*)wb)[i];
            pwv = pack4(__float2int_rn(__uint_as_float(v.x << 16)),
                        __float2int_rn(__uint_as_float(v.x & 0xFFFF0000u)),
                        __float2int_rn(__uint_as_float(v.y << 16)),
                        __float2int_rn(__uint_as_float(v.y & 0xFFFF0000u)));
        }
        swp[tid] = pwv;
    }

    // bias[f]: per-thread broadcast load + decode (matches prep logic)
    int bfil;
    {
        int v = bias[f];
        if (MODE == MODE_I8 || MODE == MODE_I32) {
            if (v >= -(1 << 20) && v <= (1 << 20)) bfil = v;
            else {
                float fb = __int_as_float(v);
                bfil = (isfinite(fb) && fabsf(fb) <= 1048576.0f && fb == rintf(fb))
                       ? (int)fb
                       : (int)__bfloat162float(((const __nv_bfloat16*)bias)[f]);
            }
        } else if (MODE == MODE_F32) {
            float fb = __int_as_float(v);
            bfil = (isfinite(fb) && fabsf(fb) <= 1048576.0f && fb == rintf(fb))
                   ? (int)fb : v;
        } else {
            bfil = (int)__bfloat162float(((const __nv_bfloat16*)bias)[f]);
        }
    }

    const long long rnd = 1LL << (tsh - 1);

    const int j0    = band * TJ;
    const int jend  = (j0 + TJ < HO_) ? (j0 + TJ) : HO_;  // exclusive output rows
    const int rlast = jend + 1;                            // last input row
    const int nrows = rlast - j0 + 1;
    const bool desc = (band & 1);                          // serpentine scan

    const int gcol = 30 * wid + lane;
    const int pcol = (gcol < W_DIM) ? gcol : (W_DIM - 1);
    const bool valid = (lane < 30) && (gcol < WO_);

    const int E = (MODE == MODE_I8) ? 1 : (MODE == MODE_BF16) ? 2 : 4;
    const size_t rs = (size_t)W_DIM * CIN * E;
    const char* xf = xb + (size_t)f * H_DIM * rs;

    int pw[16];
    phaseA<MODE>(xf + (size_t)(desc ? rlast : j0) * rs, tid, pw);   // prologue

    int s1 = 0, s2 = 0;   // rolling vertical partials

    for (int it = 0; it < nrows; ++it) {
        const int r = desc ? (rlast - it) : (j0 + it);
        int* buf = stage + (it & 1) * STAGE_WORDS;
        phaseB<MODE>(buf, tid, pw);                 // stage row r

        if (it + 1 < nrows) {                       // issue next row's LDGs early
            const int rn = desc ? (r - 1) : (r + 1);
            phaseA<MODE>(xf + (size_t)rn * rs, tid, pw);
        }

        __syncthreads();                            // row r visible (single barrier)
                                                    // (also publishes swp on it==0)

        // read own pixel column (conflict-free LDS.128: (5p+k)%8 all distinct)
        int xc[16];
        {
            const int4* xs4 = (const int4*)buf;
            const int b4 = pcol * (PIX_STRIDE / 4);
            #pragma unroll
            for (int k = 0; k < 4; ++k) {
                int4 v = xs4[b4 + k];
                xc[k * 4 + 0] = v.x; xc[k * 4 + 1] = v.y;
                xc[k * 4 + 2] = v.z; xc[k * 4 + 3] = v.w;
            }
        }

        // 9 tap dot-products over 64 channels (144 dp4a)
        int y[9];
        #pragma unroll
        for (int t = 0; t < 9; ++t) {
            const int4 w0 = ((const int4*)swp)[t * 4 + 0];
            const int4 w1 = ((const int4*)swp)[t * 4 + 1];
            const int4 w2 = ((const int4*)swp)[t * 4 + 2];
            const int4 w3 = ((const int4*)swp)[t * 4 + 3];
            int a = 0;
            a = __dp4a(xc[0],  w0.x, a);  a = __dp4a(xc[1],  w0.y, a);
            a = __dp4a(xc[2],  w0.z, a);  a = __dp4a(xc[3],  w0.w, a);
            a = __dp4a(xc[4],  w1.x, a);  a = __dp4a(xc[5],  w1.y, a);
            a = __dp4a(xc[6],  w1.z, a);  a = __dp4a(xc[7],  w1.w, a);
            a = __dp4a(xc[8],  w2.x, a);  a = __dp4a(xc[9],  w2.y, a);
            a = __dp4a(xc[10], w2.z, a);  a = __dp4a(xc[11], w2.w, a);
            a = __dp4a(xc[12], w3.x, a);  a = __dp4a(xc[13], w3.y, a);
            a = __dp4a(xc[14], w3.z, a);  a = __dp4a(xc[15], w3.w, a);
            y[t] = a;
        }

        // horizontal (n) combine
        int u0, u1, u2;
        {
            int a1 = __shfl_down_sync(0xffffffffu, y[1], 1);
            int a2 = __shfl_down_sync(0xffffffffu, y[2], 2);
            u0 = y[0] + a1 + a2;
            int b1 = __shfl_down_sync(0xffffffffu, y[4], 1);
            int b2 = __shfl_down_sync(0xffffffffu, y[5], 2);
            u1 = y[3] + b1 + b2;
            int c1 = __shfl_down_sync(0xffffffffu, y[7], 1);
            int c2 = __shfl_down_sync(0xffffffffu, y[8], 2);
            u2 = y[6] + c1 + c2;
        }

        // vertical (m) rolling combine:
        //   asc : out(j=r-2) = u2(r) + u1(r-1) + u0(r-2)
        //   desc: out(j=r)   = u0(r) + u1(r+1) + u2(r+2)
        int done;
        if (desc) { done = u0 + s1; s1 = u1 + s2; s2 = u2; }
        else      { done = s2 + u2; s2 = s1 + u1; s1 = u0; }

        if (it >= 2 && valid) {
            const int j = desc ? r : (r - 2);
            long long a64 = (long long)(done + bfil) * (long long)red + rnd;
            int res = (int)(a64 >> tsh) + ozp;
            res = res < -128 ? -128 : (res > 127 ? 127 : res);
            size_t oidx = ((size_t)(f * HO_ + j) * WO_ + gcol) * (size_t)L;
            for (int l = 0; l < L; ++l) __stcs(&outv[oidx + l], (float)res);
        }
    }
}

// ---------------------------------------------------------------------------

__global__ void __launch_bounds__(NTHR, 3)
conv_any(const char* __restrict__ xb, const char* __restrict__ wb,
         const int* __restrict__ bias,
         const int* __restrict__ s0, const int* __restrict__ s1,
         const int* __restrict__ s2,
         float* __restrict__ outv, int L)
{
    __shared__ __align__(16) int swp[144];
    __shared__ __align__(16) int stage[2 * STAGE_WORDS];   // 40 KB ping-pong
    __shared__ int cnt[4];
    __shared__ int sc[4];   // mode, red, tsh, ozp

    const int tid = threadIdx.x;

    // ---- in-kernel prep: mode sniff (parallel) + scalar decode ----
    if (tid < 4) cnt[tid] = 0;
    __syncthreads();
    if (tid < 64) {
        int c = classify_word(((const int*)xb)[tid]);
        if (c >= 0) atomicAdd(&cnt[c], 1);
    }
    __syncthreads();
    if (tid == 0) {
        int best = MODE_I8, bc = cnt[MODE_I8];
        if (cnt[MODE_I32]  > bc) { best = MODE_I32;  bc = cnt[MODE_I32]; }
        if (cnt[MODE_F32]  > bc) { best = MODE_F32;  bc = cnt[MODE_F32]; }
        if (cnt[MODE_BF16] > bc) { best = MODE_BF16; bc = cnt[MODE_BF16]; }
        sc[0] = best;

        // scalars {q_mantissa, exponent, output_zero_point}: q_mantissa is
        // huge & positive; exponent precedes ozp in both insertion and
        // alphabetical orderings.
        int qm, expv, ozp;
        int wv[3] = { s0[0], s1[0], s2[0] };
        int nh = 0, hi = -1;
        for (int i = 0; i < 3; ++i)
            if (wv[i] > 100000 || wv[i] < -100000) { ++nh; hi = i; }
        if (nh == 1 && wv[hi] > 0) {
            qm = wv[hi];
            int a = -1, b = -1;
            for (int i = 0; i < 3; ++i) if (i != hi) { if (a < 0) a = i; else b = i; }
            expv = wv[a]; ozp = wv[b];
        } else {
            float fv[3] = { __int_as_float(wv[0]), __int_as_float(wv[1]), __int_as_float(wv[2]) };
            int nh2 = 0, hi2 = -1;
            for (int i = 0; i < 3; ++i)
                if (isfinite(fv[i]) && fabsf(fv[i]) > 100000.0f) { ++nh2; hi2 = i; }
            if (nh2 == 1 && fv[hi2] > 0.0f) {
                qm = (int)(long long)fv[hi2];
                int a = -1, b = -1;
                for (int i = 0; i < 3; ++i) if (i != hi2) { if (a < 0) a = i; else b = i; }
                expv = (int)fv[a]; ozp = (int)fv[b];
            } else {
                float bv[3];
                for (int i = 0; i < 3; ++i)
                    bv[i] = __bfloat162float(__ushort_as_bfloat16((unsigned short)(wv[i] & 0xFFFF)));
                int hi3 = 0;
                for (int i = 1; i < 3; ++i) if (fabsf(bv[i]) > fabsf(bv[hi3])) hi3 = i;
                qm = (int)(long long)bv[hi3];
                int a = -1, b = -1;
                for (int i = 0; i < 3; ++i) if (i != hi3) { if (a < 0) a = i; else b = i; }
                expv = (int)bv[a]; ozp = (int)bv[b];
            }
        }
        sc[1] = (qm < 2147418112) ? ((qm + (1 << 15)) >> 16) : 32767;
        sc[2] = 15 - expv;
        sc[3] = ozp;
    }
    __syncthreads();

    const int mode = sc[0];
    const int red  = sc[1];
    const int tsh  = sc[2];
    const int ozp  = sc[3];

    if (mode == MODE_I32)
        run_conv<MODE_I32 >(xb, wb, bias, outv, L, swp, stage, red, tsh, ozp);
    else if (mode == MODE_I8)
        run_conv<MODE_I8  >(xb, wb, bias, outv, L, swp, stage, red, tsh, ozp);
    else if (mode == MODE_F32)
        run_conv<MODE_F32 >(xb, wb, bias, outv, L, swp, stage, red, tsh, ozp);
    else
        run_conv<MODE_BF16>(xb, wb, bias, outv, L, swp, stage, red, tsh, ozp);
}

// ---------------------------------------------------------------------------

extern "C" void kernel_launch(void* const* d_in, const int* in_sizes, int n_in,
                              void* d_out, int out_size)
{
    // Identify inputs BY SIZE (ordering-agnostic).
    const void* x = nullptr; const void* w = nullptr; const void* b = nullptr;
    const void* s[3] = {nullptr, nullptr, nullptr};
    int ns = 0;
    int ximax = 0;
    for (int i = 1; i < n_in; ++i)
        if (in_sizes[i] > in_sizes[ximax]) ximax = i;
    for (int i = 0; i < n_in; ++i) {
        if (i == ximax)                 x = d_in[i];
        else if (in_sizes[i] == 36864) w = d_in[i];
        else if (in_sizes[i] == 64)    b = d_in[i];
        else if (in_sizes[i] == 1 && ns < 3) s[ns++] = d_in[i];
    }
    if (!x || !w || !b || ns < 3) {
        x = d_in[0]; w = d_in[1]; b = d_in[2];
        s[0] = d_in[3]; s[1] = d_in[4]; s[2] = d_in[5];
    }

    int L = out_size / (F_DIM * HO_ * WO_);
    if (L < 1) L = 1;

    dim3 grid(NBANDS, F_DIM);
    conv_any<<<grid, NTHR>>>((const char*)x, (const char*)w, (const int*)b,
                             (const int*)s[0], (const int*)s[1], (const int*)s[2],
                             (float*)d_out, L);
}